// round 14
// baseline (speedup 1.0000x reference)
#include <cuda_runtime.h>
#include <cuda_bf16.h>

#define IN_DIM   512
#define BATCH    8192
#define GRID_NUM 48
#define NCOEF    (GRID_NUM + 3)   // 51
#define NKNOT    (GRID_NUM + 1)   // 49
#define TILE     64               // dims per block -> 8 dim-tiles
#define THREADS  256
#define NBLOCKS  888              // 148 SMs x 6 blocks: one wave
#define NSCOL    111              // slot-columns per dim-tile (888/8)
#define NSLOT    512              // BATCH/16 slots (16 rows per slot)
#define CELL_LO  24               // x in [0,1) -> t in [24,48)
#define NCELL_S  24
#define NCOL_S   27               // coef cols 24..50

__global__ __launch_bounds__(THREADS, 6) void bspline_fused_kernel(
    const float* __restrict__ x,
    const float* __restrict__ grid,
    const float* __restrict__ coef,
    float* __restrict__ y)
{
    // 4 tables by (d mod 4): [24 cells][16 quad-lanes] float4 = 6 KB each, 24 KB total.
    __shared__ float4 s_q[4 * NCELL_S * 16];
    __shared__ float  s_c[TILE * NCOL_S];      // staging: 6.75 KB

    const int tid  = threadIdx.x;
    const int bid  = blockIdx.x;
    const int dim0 = (bid & 7) * TILE;
    const int cgrp = bid >> 3;                 // 0..110 slot column

    // Stage coef cols 24..50 for 64 dims (contiguous 27-float runs, coalesced).
    for (int k = tid; k < TILE * NCOL_S; k += THREADS) {
        int d = k / NCOL_S, cc = k - d * NCOL_S;
        s_c[k] = coef[(dim0 + d) * NCOEF + CELL_LO + cc];
    }
    __syncthreads();

    // Build quad tables (s_c reads stride 27: conflict-free).
    for (int k = tid; k < NCELL_S * TILE; k += THREADS) {
        int cell = k >> 6, d = k & (TILE - 1);
        const float* p = s_c + d * NCOL_S + cell;
        float c0 = p[0], c1 = p[1], c2 = p[2], c3 = p[3];
        float4 a;
        a.x = (c0 + 4.0f * c1 + c2) * (1.0f / 6.0f);
        a.y = (c2 - c0) * 0.5f;
        a.z = (c0 - 2.0f * c1 + c2) * 0.5f;
        a.w = (c3 - c0 + 3.0f * (c1 - c2)) * (1.0f / 6.0f);
        s_q[(d & 3) * (NCELL_S * 16) + cell * 16 + (d >> 2)] = a;
    }

    const int i    = tid & 15;                 // quad lane (16 per row-half)
    const int rofs = tid >> 4;                 // 0..15 row within slot
    const int colb = dim0 + 4 * i;             // first of this thread's 4 dims

    float A[4], B[4];
    #pragma unroll
    for (int m = 0; m < 4; ++m) {
        float lo = grid[(colb + m) * NKNOT];
        float hi = grid[(colb + m) * NKNOT + GRID_NUM];
        A[m] = (float)GRID_NUM / (hi - lo);
        B[m] = fmaf(-lo, A[m], -(float)CELL_LO);
    }

    __syncthreads();

    const float4* __restrict__ x4 = (const float4*)x;
    float4* __restrict__ y4 = (float4*)y;
    const float4* tab = s_q + i;               // + m*384 + cs*16 per access

    const int quad    = (dim0 >> 2) + i;       // float4 column, 0..127
    const int idx0    = (cgrp * 16 + rofs) * (IN_DIM / 4) + quad;
    const int SSTEP   = NSCOL * 16 * (IN_DIM / 4);             // 227328
    const int idx_max = ((NSLOT - 1) * 16 + rofs) * (IN_DIM / 4) + quad;

    // All 5 slot indices; k=0..3 in-range (cgrp+3*111 <= 443 < 512), k=4 clamped
    // (duplicate rows write identical deterministic values).
    int idx[5];
    #pragma unroll
    for (int k = 0; k < 5; ++k) idx[k] = idx0 + k * SSTEP;
    idx[4] = min(idx[4], idx_max);

    // Load everything up-front: 5 independent LDG.128 (MLP=5 covering whole workload).
    float4 v[5];
    #pragma unroll
    for (int k = 0; k < 5; ++k) v[k] = x4[idx[k]];

    // Evaluate in place, store per slot.
    #pragma unroll
    for (int k = 0; k < 5; ++k) {
        float* e = reinterpret_cast<float*>(&v[k]);
        #pragma unroll
        for (int m = 0; m < 4; ++m) {
            float tf = fmaf(e[m], A[m], B[m]);  // t - 24
            int cs = __float2int_rd(tf);
            float r;
            if (__builtin_expect((unsigned)cs < (unsigned)NCELL_S, 1)) {
                float u = tf - (float)cs;
                float4 a = tab[m * (NCELL_S * 16) + cs * 16];  // conflict-free LDS.128
                r = fmaf(fmaf(fmaf(a.w, u, a.z), u, a.y), u, a.x);
            } else {                            // inline cold path; never taken in-range
                float t = tf + (float)CELL_LO;
                int cell = max(0, min(__float2int_rd(t), GRID_NUM - 1));
                float u = t - (float)cell;
                const float* p = coef + (colb + m) * NCOEF + cell;
                float c0 = p[0], c1 = p[1], c2 = p[2], c3 = p[3];
                float ax = (c0 + 4.0f * c1 + c2) * (1.0f / 6.0f);
                float ay = (c2 - c0) * 0.5f;
                float az = (c0 - 2.0f * c1 + c2) * 0.5f;
                float aw = (c3 - c0 + 3.0f * (c1 - c2)) * (1.0f / 6.0f);
                r = fmaf(fmaf(fmaf(aw, u, az), u, ay), u, ax);
            }
            e[m] = r;
        }
        y4[idx[k]] = v[k];                      // STG.128
    }
}

extern "C" void kernel_launch(void* const* d_in, const int* in_sizes, int n_in,
                              void* d_out, int out_size) {
    const float* x    = (const float*)d_in[0];
    const float* grid = (const float*)d_in[1];
    const float* coef = (const float*)d_in[2];
    float* y = (float*)d_out;

    bspline_fused_kernel<<<NBLOCKS, THREADS>>>(x, grid, coef, y);
}

// round 16
// speedup vs baseline: 1.3221x; 1.3221x over previous
#include <cuda_runtime.h>
#include <cuda_bf16.h>

#define IN_DIM   512
#define BATCH    8192
#define GRID_NUM 48
#define NCOEF    (GRID_NUM + 3)   // 51
#define NKNOT    (GRID_NUM + 1)   // 49
#define TILE     64               // dims per block -> 8 dim-tiles
#define THREADS  256
#define NBLOCKS  888              // 148 SMs x 6 blocks: exactly one wave
#define NRG      111              // row-group columns per dim-tile (888/8)
#define NRG_TOT  2048             // BATCH/4
#define CELL_LO  24               // x in [0,1) -> t in [24,48)
#define NCELL_S  24               // staged cells 24..47
#define NCOL_S   27               // coef columns needed: 24..50

__global__ __launch_bounds__(THREADS, 6) void bspline_fused_kernel(
    const float* __restrict__ x,
    const float* __restrict__ grid,
    const float* __restrict__ coef,
    float* __restrict__ y)
{
    __shared__ float4 s_quad[NCELL_S * TILE];   // 24.0 KB, [cell-24][d]
    __shared__ float  s_c[TILE * NCOL_S];       //  6.9 KB, [d][c-24]

    const int tid  = threadIdx.x;
    const int bid  = blockIdx.x;
    const int dim0 = (bid & 7) * TILE;
    const int rg0  = bid >> 3;                  // 0..110

    // Stage coef columns 24..50 for this block's 64 dims (contiguous 27-float runs).
    #pragma unroll
    for (int k = tid; k < TILE * NCOL_S; k += THREADS) {
        int d = k / NCOL_S, c = k - d * NCOL_S;
        s_c[k] = coef[(dim0 + d) * NCOEF + CELL_LO + c];
    }
    __syncthreads();

    // Build monomial quad table: s_c stride-27 LDS conflict-free; STS.128 banks 4d mod 32.
    #pragma unroll
    for (int k = tid; k < NCELL_S * TILE; k += THREADS) {
        int cell = k >> 6, d = k & (TILE - 1);
        const float* c = s_c + d * NCOL_S + cell;
        float c0 = c[0], c1 = c[1], c2 = c[2], c3 = c[3];
        float4 a;
        a.x = (c0 + 4.0f * c1 + c2) * (1.0f / 6.0f);
        a.y = (c2 - c0) * 0.5f;
        a.z = (c0 - 2.0f * c1 + c2) * 0.5f;
        a.w = (c3 - c0 + 3.0f * (c1 - c2)) * (1.0f / 6.0f);
        s_quad[k] = a;
    }

    const int d    = tid & (TILE - 1);
    const int rofs = tid >> 6;                  // 0..3
    const int col  = dim0 + d;
    const float glo = grid[col * NKNOT];
    const float ghi = grid[col * NKNOT + GRID_NUM];
    const float A   = (float)GRID_NUM / (ghi - glo);
    const float B   = fmaf(-glo, A, -(float)CELL_LO);   // t - 24 = fma(x, A, B)

    __syncthreads();

    const int idx0    = (rg0 * 4 + rofs) * IN_DIM + col;
    const int max_idx = ((NRG_TOT - 1) * 4 + rofs) * IN_DIM + col;
    const int Q_OFF   = NRG * 4 * IN_DIM;       // 227328: per q-slot offset
    const int IT_OFF  = 4 * Q_OFF;

    // 5 iterations x q=4 = 20 slots: j=0..17 in-range (110+17*111=1997<2048);
    // j=18,19 (inside it=4) clamped -> duplicate rows write identical values.
    #pragma unroll
    for (int it = 0; it < 5; ++it) {
        const int base = idx0 + it * IT_OFF;
        float xv[4], res[4];
        #pragma unroll
        for (int q = 0; q < 4; ++q) {           // MLP=4 streaming loads
            int idx = base + q * Q_OFF;
            if (it == 4) idx = min(idx, max_idx);
            xv[q] = x[idx];
        }
        #pragma unroll
        for (int q = 0; q < 4; ++q) {
            float tf = fmaf(xv[q], A, B);       // t - 24
            int cs = __float2int_rd(tf);
            float r;
            if (__builtin_expect((unsigned)cs < (unsigned)NCELL_S, 1)) {
                float u = tf - (float)cs;
                float4 a = s_quad[cs * TILE + d];   // conflict-free LDS.128
                r = fmaf(fmaf(fmaf(a.w, u, a.z), u, a.y), u, a.x);
            } else {                            // inline cold path; never taken in-range
                float t = tf + (float)CELL_LO;
                int cell = max(0, min(__float2int_rd(t), GRID_NUM - 1));
                float u = t - (float)cell;
                const float* c = coef + col * NCOEF + cell;
                float c0 = c[0], c1 = c[1], c2 = c[2], c3 = c[3];
                float ax = (c0 + 4.0f * c1 + c2) * (1.0f / 6.0f);
                float ay = (c2 - c0) * 0.5f;
                float az = (c0 - 2.0f * c1 + c2) * 0.5f;
                float aw = (c3 - c0 + 3.0f * (c1 - c2)) * (1.0f / 6.0f);
                r = fmaf(fmaf(fmaf(aw, u, az), u, ay), u, ax);
            }
            res[q] = r;
        }
        #pragma unroll
        for (int q = 0; q < 4; ++q) {
            int idx = base + q * Q_OFF;
            if (it == 4) idx = min(idx, max_idx);
            y[idx] = res[q];
        }
    }
}

extern "C" void kernel_launch(void* const* d_in, const int* in_sizes, int n_in,
                              void* d_out, int out_size) {
    const float* x    = (const float*)d_in[0];
    const float* grid = (const float*)d_in[1];
    const float* coef = (const float*)d_in[2];
    float* y = (float*)d_out;

    bspline_fused_kernel<<<NBLOCKS, THREADS>>>(x, grid, coef, y);
}

// round 17
// speedup vs baseline: 1.3646x; 1.0322x over previous
#include <cuda_runtime.h>
#include <cuda_bf16.h>

#define IN_DIM   512
#define BATCH    8192
#define GRID_NUM 48
#define NCOEF    (GRID_NUM + 3)   // 51
#define NKNOT    (GRID_NUM + 1)   // 49
#define TILE     32               // dims per block -> 16 dim-tiles
#define THREADS  256
#define NBLOCKS  880              // 16 tiles x 55 row-cols; <= 888 -> one wave
#define NSCOL    55               // row-slot columns per dim-tile
#define NSLOT    1024             // BATCH/8 slots (8 rows per slot)
#define CELL_LO  24               // x in [0,1) -> t in [24,48)
#define NCELL_S  24               // staged cells 24..47
#define NCOL_S   27               // coef columns needed: 24..50

__global__ __launch_bounds__(THREADS, 6) void bspline_fused_kernel(
    const float* __restrict__ x,
    const float* __restrict__ grid,
    const float* __restrict__ coef,
    float* __restrict__ y)
{
    __shared__ float4 s_quad[NCELL_S * TILE];   // 12.0 KB, [cell-24][d]
    __shared__ float  s_c[TILE * NCOL_S];       //  3.4 KB, [d][c-24]

    const int tid  = threadIdx.x;
    const int bid  = blockIdx.x;
    const int dim0 = (bid & 15) * TILE;
    const int cgrp = bid >> 4;                  // 0..54

    // Stage coef columns 24..50 for this block's 32 dims (contiguous 27-float runs).
    #pragma unroll
    for (int k = tid; k < TILE * NCOL_S; k += THREADS) {
        int d = k / NCOL_S, c = k - d * NCOL_S;
        s_c[k] = coef[(dim0 + d) * NCOEF + CELL_LO + c];
    }
    __syncthreads();

    // Build quad table: 3 iters/thread. s_c reads stride-27 (coprime 32): conflict-free.
    #pragma unroll
    for (int k = tid; k < NCELL_S * TILE; k += THREADS) {
        int cell = k >> 5, d = k & (TILE - 1);
        const float* c = s_c + d * NCOL_S + cell;
        float c0 = c[0], c1 = c[1], c2 = c[2], c3 = c[3];
        float4 a;
        a.x = (c0 + 4.0f * c1 + c2) * (1.0f / 6.0f);
        a.y = (c2 - c0) * 0.5f;
        a.z = (c0 - 2.0f * c1 + c2) * 0.5f;
        a.w = (c3 - c0 + 3.0f * (c1 - c2)) * (1.0f / 6.0f);
        s_quad[k] = a;
    }

    const int d    = tid & (TILE - 1);          // 0..31: warp lanes = consecutive dims
    const int rofs = tid >> 5;                  // 0..7 row within slot
    const int col  = dim0 + d;
    const float glo = grid[col * NKNOT];
    const float ghi = grid[col * NKNOT + GRID_NUM];
    const float A   = (float)GRID_NUM / (ghi - glo);
    const float B   = fmaf(-glo, A, -(float)CELL_LO);   // t - 24 = fma(x, A, B)

    __syncthreads();

    const int idx0    = (cgrp * 8 + rofs) * IN_DIM + col;
    const int max_idx = ((NSLOT - 1) * 8 + rofs) * IN_DIM + col;
    const int Q_OFF   = NSCOL * 8 * IN_DIM;     // 225280: per slot-step offset
    const int IT_OFF  = 4 * Q_OFF;

    // 5 iterations x q=4 = 20 slots: j=0..15 in-range (54+15*55=879<1024);
    // it=4: j=16,17 clamp is a no-op; j=18,19 duplicate rows write identical values.
    #pragma unroll
    for (int it = 0; it < 5; ++it) {
        const int base = idx0 + it * IT_OFF;
        float xv[4], res[4];
        #pragma unroll
        for (int q = 0; q < 4; ++q) {           // MLP=4 streaming loads
            int idx = base + q * Q_OFF;
            if (it == 4) idx = min(idx, max_idx);
            xv[q] = x[idx];
        }
        #pragma unroll
        for (int q = 0; q < 4; ++q) {
            float tf = fmaf(xv[q], A, B);       // t - 24
            int cs = __float2int_rd(tf);
            float r;
            if (__builtin_expect((unsigned)cs < (unsigned)NCELL_S, 1)) {
                float u = tf - (float)cs;
                float4 a = s_quad[cs * TILE + d];   // conflict-free LDS.128
                r = fmaf(fmaf(fmaf(a.w, u, a.z), u, a.y), u, a.x);
            } else {                            // inline cold path; never taken in-range
                float t = tf + (float)CELL_LO;
                int cell = max(0, min(__float2int_rd(t), GRID_NUM - 1));
                float u = t - (float)cell;
                const float* c = coef + col * NCOEF + cell;
                float c0 = c[0], c1 = c[1], c2 = c[2], c3 = c[3];
                float ax = (c0 + 4.0f * c1 + c2) * (1.0f / 6.0f);
                float ay = (c2 - c0) * 0.5f;
                float az = (c0 - 2.0f * c1 + c2) * 0.5f;
                float aw = (c3 - c0 + 3.0f * (c1 - c2)) * (1.0f / 6.0f);
                r = fmaf(fmaf(fmaf(aw, u, az), u, ay), u, ax);
            }
            res[q] = r;
        }
        #pragma unroll
        for (int q = 0; q < 4; ++q) {
            int idx = base + q * Q_OFF;
            if (it == 4) idx = min(idx, max_idx);
            y[idx] = res[q];
        }
    }
}

extern "C" void kernel_launch(void* const* d_in, const int* in_sizes, int n_in,
                              void* d_out, int out_size) {
    const float* x    = (const float*)d_in[0];
    const float* grid = (const float*)d_in[1];
    const float* coef = (const float*)d_in[2];
    float* y = (float*)d_out;

    bspline_fused_kernel<<<NBLOCKS, THREADS>>>(x, grid, coef, y);
}